// round 4
// baseline (speedup 1.0000x reference)
#include <cuda_runtime.h>

#define EPS 1e-12f
#define TPB 256        // threads per block
#define PPB 1024       // points per block (PPB = 4*TPB)

__global__ __launch_bounds__(TPB, 6) void blinn_phong_kernel(
    const float* __restrict__ in,   // [n, 3, 3]
    const float* __restrict__ kd,   // [3]
    const float* __restrict__ ks,   // [3]
    const float* __restrict__ pp,   // [1]
    float* __restrict__ out,        // [n, 3]
    int n)
{
    __shared__ float s_in[PPB * 9];    // 36 KB

    const int tid  = threadIdx.x;
    const int base = blockIdx.x * PPB;
    const int npts = min(PPB, n - base);

    // Broadcast material params (uniform across warp)
    const float kd0 = kd[0], kd1 = kd[1], kd2 = kd[2];
    const float ks0 = ks[0], ks1 = ks[1], ks2 = ks[2];
    const float p   = pp[0];

    // ---- Stage 1: coalesced global -> smem (9 independent LDG.128 per thread)
    if (npts == PPB) {
        const float4* g4 = reinterpret_cast<const float4*>(in + (size_t)base * 9);
        float4* s4 = reinterpret_cast<float4*>(s_in);
        #pragma unroll
        for (int i = 0; i < (PPB * 9) / 4 / TPB; ++i)
            s4[tid + i * TPB] = g4[tid + i * TPB];
    } else {
        const int nflt = npts * 9;
        for (int i = tid; i < nflt; i += TPB)
            s_in[i] = in[(size_t)base * 9 + i];
    }
    __syncthreads();

    // ---- Stage 2: compute; write straight to global.
    // smem reads stride-9 (coprime w/ 32 banks: conflict-free).
    // Global stores: warp covers 384 contiguous bytes; L2 merges partial sectors.
    #pragma unroll
    for (int k = 0; k < PPB / TPB; ++k) {
        const int pt = tid + k * TPB;
        if (pt < npts) {
            const float* q = s_in + pt * 9;
            float lx = q[0], ly = q[1], lz = q[2];
            float nx = q[3], ny = q[4], nz = q[5];
            float vx = q[6], vy = q[7], vz = q[8];

            // diffuse
            float ln = fmaxf(0.0f, lx * nx + ly * ny + lz * nz);

            // half vector (unnormalized) + norm
            float hx = lx + vx, hy = ly + vy, hz = lz + vz;
            float hh = hx * hx + hy * hy + hz * hz;
            float norm = fmaxf(sqrtf(hh), EPS);

            // nh = max(0, dot(n,h)) / norm  (norm > 0)
            float ndh = fmaxf(0.0f, nx * hx + ny * hy + nz * hz) / norm;

            // specular: nh^p  (__powf(0,p)=0 for p>0 — matches reference)
            float s = __powf(ndh, p);

            float* o = out + (size_t)(base + pt) * 3;
            o[0] = ks0 * s + kd0 * ln;
            o[1] = ks1 * s + kd1 * ln;
            o[2] = ks2 * s + kd2 * ln;
        }
    }
}

extern "C" void kernel_launch(void* const* d_in, const int* in_sizes, int n_in,
                              void* d_out, int out_size)
{
    const float* in = (const float*)d_in[0];   // [N,3,3]
    const float* kd = (const float*)d_in[1];   // [3]
    const float* ks = (const float*)d_in[2];   // [3]
    const float* p  = (const float*)d_in[3];   // [1]
    float* out = (float*)d_out;                // [N,3]

    const int n = in_sizes[0] / 9;
    const int grid = (n + PPB - 1) / PPB;
    blinn_phong_kernel<<<grid, TPB>>>(in, kd, ks, p, out, n);
}

// round 5
// speedup vs baseline: 1.0221x; 1.0221x over previous
#include <cuda_runtime.h>

#define EPS 1e-12f
#define TPB 256        // threads per block
#define PPB 1024       // points per block (PPB = 4*TPB)

__global__ __launch_bounds__(TPB, 6) void blinn_phong_kernel(
    const float* __restrict__ in,   // [n, 3, 3]
    const float* __restrict__ kd,   // [3]
    const float* __restrict__ ks,   // [3]
    const float* __restrict__ pp,   // [1]
    float* __restrict__ out,        // [n, 3]
    int n)
{
    // Single buffer, reused: input staging (PPB*9 floats), then the first
    // PPB*3 floats are overwritten with outputs after all reads complete.
    __shared__ float s[PPB * 9];    // 36 KB -> 6 CTAs/SM

    const int tid  = threadIdx.x;
    const int base = blockIdx.x * PPB;
    const int npts = min(PPB, n - base);

    const float kd0 = kd[0], kd1 = kd[1], kd2 = kd[2];
    const float ks0 = ks[0], ks1 = ks[1], ks2 = ks[2];
    const float p   = pp[0];

    // ---- Stage 1: coalesced global -> smem (9 LDG.128 per thread, batched)
    if (npts == PPB) {
        const float4* g4 = reinterpret_cast<const float4*>(in + (size_t)base * 9);
        float4* s4 = reinterpret_cast<float4*>(s);
        #pragma unroll
        for (int i = 0; i < (PPB * 9) / 4 / TPB; ++i)   // 9 iters
            s4[tid + i * TPB] = g4[tid + i * TPB];
    } else {
        const int nflt = npts * 9;
        for (int i = tid; i < nflt; i += TPB)
            s[i] = in[(size_t)base * 9 + i];
    }
    __syncthreads();

    // ---- Stage 2: compute 4 points into registers.
    // smem reads stride-9 across lanes (coprime w/ 32 banks: conflict-free).
    float r[PPB / TPB][3];
    #pragma unroll
    for (int k = 0; k < PPB / TPB; ++k) {
        const int pt = tid + k * TPB;
        if (pt < npts) {
            const float* q = s + pt * 9;
            float lx = q[0], ly = q[1], lz = q[2];
            float nx = q[3], ny = q[4], nz = q[5];
            float vx = q[6], vy = q[7], vz = q[8];

            float ln = fmaxf(0.0f, lx * nx + ly * ny + lz * nz);

            float hx = lx + vx, hy = ly + vy, hz = lz + vz;
            float hh = hx * hx + hy * hy + hz * hz;
            float norm = fmaxf(sqrtf(hh), EPS);

            float ndh = fmaxf(0.0f, nx * hx + ny * hy + nz * hz) / norm;
            float sp  = __powf(ndh, p);   // __powf(0,p)=0 for p>0 — matches ref

            r[k][0] = ks0 * sp + kd0 * ln;
            r[k][1] = ks1 * sp + kd1 * ln;
            r[k][2] = ks2 * sp + kd2 * ln;
        }
    }
    __syncthreads();   // all smem reads done — safe to overwrite

    // ---- Stage 3: registers -> smem (stride-3: conflict-free)
    #pragma unroll
    for (int k = 0; k < PPB / TPB; ++k) {
        const int pt = tid + k * TPB;
        if (pt < npts) {
            float* o = s + pt * 3;
            o[0] = r[k][0];
            o[1] = r[k][1];
            o[2] = r[k][2];
        }
    }
    __syncthreads();

    // ---- Stage 4: coalesced smem -> global (3 STG.128 per thread)
    if (npts == PPB) {
        const float4* s4 = reinterpret_cast<const float4*>(s);
        float4* g4 = reinterpret_cast<float4*>(out + (size_t)base * 3);
        #pragma unroll
        for (int i = 0; i < (PPB * 3) / 4 / TPB; ++i)   // 3 iters
            g4[tid + i * TPB] = s4[tid + i * TPB];
    } else {
        const int nflt = npts * 3;
        for (int i = tid; i < nflt; i += TPB)
            out[(size_t)base * 3 + i] = s[i];
    }
}

extern "C" void kernel_launch(void* const* d_in, const int* in_sizes, int n_in,
                              void* d_out, int out_size)
{
    const float* in = (const float*)d_in[0];   // [N,3,3]
    const float* kd = (const float*)d_in[1];   // [3]
    const float* ks = (const float*)d_in[2];   // [3]
    const float* p  = (const float*)d_in[3];   // [1]
    float* out = (float*)d_out;                // [N,3]

    const int n = in_sizes[0] / 9;
    const int grid = (n + PPB - 1) / PPB;
    blinn_phong_kernel<<<grid, TPB>>>(in, kd, ks, p, out, n);
}

// round 6
// speedup vs baseline: 1.2602x; 1.2330x over previous
#include <cuda_runtime.h>
#include <cstdint>

#define EPS 1e-12f
#define TPB 256        // threads per block
#define PPB 1024       // points per block
#define IN_BYTES  (PPB * 9 * 4)   // 36864
#define OUT_BYTES (PPB * 3 * 4)   // 12288

__device__ __forceinline__ uint32_t smem_u32(const void* p) {
    uint32_t a;
    asm("{ .reg .u64 t; cvta.to.shared.u64 t, %1; cvt.u32.u64 %0, t; }"
        : "=r"(a) : "l"(p));
    return a;
}

__global__ __launch_bounds__(TPB, 6) void blinn_phong_kernel(
    const float* __restrict__ in,   // [n, 3, 3]
    const float* __restrict__ kd,   // [3]
    const float* __restrict__ ks,   // [3]
    const float* __restrict__ pp,   // [1]
    float* __restrict__ out,        // [n, 3]
    int n)
{
    // Reused buffer: staged input (PPB*9 floats); front PPB*3 floats are
    // overwritten with outputs once all reads are complete.
    __shared__ alignas(16) float s[PPB * 9];   // 36 KB
    __shared__ alignas(8)  uint64_t mbar;

    const int tid  = threadIdx.x;
    const int base = blockIdx.x * PPB;
    const int npts = min(PPB, n - base);

    const float kd0 = kd[0], kd1 = kd[1], kd2 = kd[2];
    const float ks0 = ks[0], ks1 = ks[1], ks2 = ks[2];
    const float p   = pp[0];

    const uint32_t s_addr = smem_u32(s);
    const uint32_t m_addr = smem_u32(&mbar);

    // ---- Stage 1: bulk-async global -> smem (one 36 KB UBLKCP per CTA) ----
    if (npts == PPB) {
        if (tid == 0) {
            asm volatile("mbarrier.init.shared.b64 [%0], 1;"
                         :: "r"(m_addr) : "memory");
        }
        __syncthreads();
        if (tid == 0) {
            asm volatile("mbarrier.arrive.expect_tx.shared.b64 _, [%0], %1;"
                         :: "r"(m_addr), "r"((uint32_t)IN_BYTES) : "memory");
            asm volatile(
                "cp.async.bulk.shared::cluster.global.mbarrier::complete_tx::bytes"
                " [%0], [%1], %2, [%3];"
                :: "r"(s_addr), "l"(in + (size_t)base * 9),
                   "r"((uint32_t)IN_BYTES), "r"(m_addr)
                : "memory");
        }
        // All threads wait for the bulk copy (phase 0 -> 1)
        {
            uint32_t done;
            asm volatile(
                "{\n\t.reg .pred P;\n\t"
                "mbarrier.try_wait.parity.acquire.cta.shared::cta.b64 P, [%1], 0;\n\t"
                "selp.b32 %0, 1, 0, P;\n\t}"
                : "=r"(done) : "r"(m_addr) : "memory");
            if (!done) {
                asm volatile(
                    "{\n\t.reg .pred P;\n\t"
                    "WL_%=:\n\t"
                    "mbarrier.try_wait.parity.acquire.cta.shared::cta.b64 P, [%0], 0, 0x989680;\n\t"
                    "@P bra.uni WD_%=;\n\t"
                    "bra.uni WL_%=;\n\t"
                    "WD_%=:\n\t}"
                    :: "r"(m_addr) : "memory");
            }
        }
    } else {
        // ragged tail fallback (not hit for N = 4M)
        const int nflt = npts * 9;
        for (int i = tid; i < nflt; i += TPB)
            s[i] = in[(size_t)base * 9 + i];
        __syncthreads();
    }

    // ---- Stage 2: compute 4 points into registers.
    // smem reads stride-9 across lanes (coprime with 32 banks: conflict-free)
    float r[PPB / TPB][3];
    #pragma unroll
    for (int k = 0; k < PPB / TPB; ++k) {
        const int pt = tid + k * TPB;
        if (pt < npts) {
            const float* q = s + pt * 9;
            float lx = q[0], ly = q[1], lz = q[2];
            float nx = q[3], ny = q[4], nz = q[5];
            float vx = q[6], vy = q[7], vz = q[8];

            float ln = fmaxf(0.0f, lx * nx + ly * ny + lz * nz);

            float hx = lx + vx, hy = ly + vy, hz = lz + vz;
            float hh = hx * hx + hy * hy + hz * hz;
            float norm = fmaxf(sqrtf(hh), EPS);

            float ndh = fmaxf(0.0f, nx * hx + ny * hy + nz * hz) / norm;
            float sp  = __powf(ndh, p);   // __powf(0,p)=0 for p>0 — matches ref

            r[k][0] = ks0 * sp + kd0 * ln;
            r[k][1] = ks1 * sp + kd1 * ln;
            r[k][2] = ks2 * sp + kd2 * ln;
        }
    }
    __syncthreads();   // all smem reads done — safe to overwrite front 12 KB

    // ---- Stage 3: registers -> smem (stride-3: conflict-free) ----
    #pragma unroll
    for (int k = 0; k < PPB / TPB; ++k) {
        const int pt = tid + k * TPB;
        if (pt < npts) {
            float* o = s + pt * 3;
            o[0] = r[k][0];
            o[1] = r[k][1];
            o[2] = r[k][2];
        }
    }
    __syncthreads();

    // ---- Stage 4: bulk-async smem -> global (one 12 KB UBLKCP per CTA) ----
    if (npts == PPB) {
        if (tid == 0) {
            asm volatile("fence.proxy.async.shared::cta;" ::: "memory");
            asm volatile(
                "cp.async.bulk.global.shared::cta.bulk_group [%0], [%1], %2;"
                :: "l"(out + (size_t)base * 3), "r"(s_addr),
                   "r"((uint32_t)OUT_BYTES)
                : "memory");
            asm volatile("cp.async.bulk.commit_group;" ::: "memory");
            // hold smem alive until the store has read it
            asm volatile("cp.async.bulk.wait_group.read 0;" ::: "memory");
        }
    } else {
        const int nflt = npts * 3;
        for (int i = tid; i < nflt; i += TPB)
            out[(size_t)base * 3 + i] = s[i];
    }
}

extern "C" void kernel_launch(void* const* d_in, const int* in_sizes, int n_in,
                              void* d_out, int out_size)
{
    const float* in = (const float*)d_in[0];   // [N,3,3]
    const float* kd = (const float*)d_in[1];   // [3]
    const float* ks = (const float*)d_in[2];   // [3]
    const float* p  = (const float*)d_in[3];   // [1]
    float* out = (float*)d_out;                // [N,3]

    const int n = in_sizes[0] / 9;
    const int grid = (n + PPB - 1) / PPB;
    blinn_phong_kernel<<<grid, TPB>>>(in, kd, ks, p, out, n);
}